// round 17
// baseline (speedup 1.0000x reference)
#include <cuda_runtime.h>
#include <cuda_fp16.h>
#include <cstdint>
#include <cstddef>

// ---------------------------------------------------------------------------
// Problem constants
// ---------------------------------------------------------------------------
#define BATCH 8
#define CH    512
#define CQD   64
#define HW    4096
#define M2TOT 320          // K1a packed rows: pq,pk,cq,ck,cv
#define M2PAD 384
#define YROWS 192          // fp32 Y rows per batch (cq,ck,cv)

// scratch layout (float offsets)
#define OFF_BI   0u            // BI2 [384] at 0, BIV [512] at 384
#define OFF_W2H  1024u         // [384,512] fp16
#define OFF_W2L  99328u
#define OFF_WVH  197632u       // [512,512] fp16 (v weights, hi only)
#define OFF_XH   328704u       // [8,512,4096] fp16
#define OFF_Y    8717312u      // [8,192,4096] fp32 (cq,ck,cv)
#define OFF_QTH  15008768u     // [8,4096,64] fp16
#define OFF_KH   16057344u     // [8,64,4096] fp16
#define OFF_VH   17105920u     // [8,512,4096] fp16
#define OFF_PH   25494528u     // PE fp16 [8,4096,4096]
#define OFF_PART 92603392u     // [8,32,4096] fp32
#define OFF_ZINV 93651968u
#define OFF_CE   93684736u
#define OFF_CEP  93717504u
#define OFF_CO   94241792u
#define SCRATCH_FLOATS 96338944u

__device__ float g_scratch[SCRATCH_FLOATS];

// ---------------------------------------------------------------------------
// PTX helpers
// ---------------------------------------------------------------------------
__device__ __forceinline__ uint32_t smem_to_u32(const void* p) {
    uint32_t a;
    asm("{ .reg .u64 t; cvta.to.shared.u64 t, %1; cvt.u32.u64 %0, t; }" : "=r"(a) : "l"(p));
    return a;
}

__device__ __forceinline__ void ldsm4(uint32_t* r, uint32_t addr) {
    asm volatile("ldmatrix.sync.aligned.m8n8.x4.shared.b16 {%0,%1,%2,%3}, [%4];"
                 : "=r"(r[0]), "=r"(r[1]), "=r"(r[2]), "=r"(r[3]) : "r"(addr));
}
__device__ __forceinline__ void ldsm4t(uint32_t* r, uint32_t addr) {
    asm volatile("ldmatrix.sync.aligned.m8n8.x4.trans.shared.b16 {%0,%1,%2,%3}, [%4];"
                 : "=r"(r[0]), "=r"(r[1]), "=r"(r[2]), "=r"(r[3]) : "r"(addr));
}
__device__ __forceinline__ void mma16816(float* c, const uint32_t* a,
                                         uint32_t b0, uint32_t b1) {
    asm volatile("mma.sync.aligned.m16n8k16.row.col.f32.f16.f16.f32 "
                 "{%0,%1,%2,%3}, {%4,%5,%6,%7}, {%8,%9}, {%0,%1,%2,%3};"
                 : "+f"(c[0]), "+f"(c[1]), "+f"(c[2]), "+f"(c[3])
                 : "r"(a[0]), "r"(a[1]), "r"(a[2]), "r"(a[3]), "r"(b0), "r"(b1));
}
__device__ __forceinline__ void cp16(uint32_t dst, const void* src) {
    asm volatile("cp.async.cg.shared.global [%0], [%1], 16;" :: "r"(dst), "l"(src));
}
#define CP_COMMIT() asm volatile("cp.async.commit_group;" ::: "memory")

// ---------------------------------------------------------------------------
// fp16-split GEMM via mma.sync (HMMA) — proven R8/R12 config.
// Epilogue modes (checked in order):
//   KHo != nullptr : K1a routing — row<64 -> QTo transposed fp16;
//       row<128 -> KHo fp16; row<320 -> fp32 C at (row-128); else skip.
//   VHo != nullptr : K1b — all rows -> VHo fp16 (+bias)
//   PEo != nullptr : K2 exp epilogue (PE fp16 + row-sum partials)
//   else           : fp32 C (+bias)
// ---------------------------------------------------------------------------
template<int AT, int BK, int NST, int BN, int OCC>
__global__ void __launch_bounds__(256, OCC) gemm_mma(
    const __half* __restrict__ Ah, const __half* __restrict__ Al,
    const __half* __restrict__ Bh,
    const float* __restrict__ bias, float* __restrict__ C,
    int K, int lda, int ldb, int ldc,
    size_t sA, size_t sB, size_t sC, int has_bias,
    __half* __restrict__ QTo, __half* __restrict__ KHo, __half* __restrict__ VHo,
    __half* __restrict__ PEo, float* __restrict__ Part)
{
    constexpr int APITCH = BK + 8;
    constexpr int BPITCH = BN + 8;
    constexpr int A_STG  = 128 * APITCH * 2;
    constexpr int B_STG  = BK * BPITCH * 2;
    constexpr int STG_BYTES = AT * A_STG + B_STG;
    constexpr int ATPR  = BK / 8;
    constexpr int AROWS = 256 / ATPR;
    constexpr int NPASS = 128 / AROWS;
    constexpr int BTPR  = BN / 8;
    constexpr int BROWS = 256 / BTPR;
    constexpr int BPASS = BK / BROWS;
    constexpr int KS    = BK / 16;
    constexpr int NJ    = BN / 32;
    constexpr int WN    = BN / 2;

    extern __shared__ char smem[];
    __shared__ float sred[2][128];
    const uint32_t sb = smem_to_u32(smem);
    const int tid  = threadIdx.x;
    const int w    = tid >> 5, lane = tid & 31;
    const int wm   = w & 3,    wn   = w >> 2;
    const int b    = blockIdx.z;
    const int m0   = blockIdx.x * 128, n0 = blockIdx.y * BN;

    const __half* Ag[AT];
    Ag[0] = Ah + (size_t)b * sA + (size_t)m0 * lda;
    if (AT == 2) Ag[1] = Al + (size_t)b * sA + (size_t)m0 * lda;
    const __half* Bg0 = Bh + (size_t)b * sB + n0;

    const int nk = K / BK;

    const int a_row = tid / ATPR, a_ch = (tid % ATPR) << 3;
    const int b_row = tid / BTPR, b_ch = (tid % BTPR) << 3;

    auto issue = [&](int stage, int kt) {
        const uint32_t base = sb + stage * STG_BYTES;
        const int k0 = kt * BK;
#pragma unroll
        for (int h = 0; h < AT; h++) {
            const __half* asrc = Ag[h] + k0;
            const uint32_t adst = base + h * A_STG;
#pragma unroll
            for (int r = 0; r < NPASS; r++) {
                int row = a_row + r * AROWS;
                cp16(adst + (uint32_t)(row * APITCH + a_ch) * 2,
                     asrc + (size_t)row * lda + a_ch);
            }
        }
        {
            const uint32_t bdst = base + AT * A_STG;
#pragma unroll
            for (int r = 0; r < BPASS; r++) {
                int row = b_row + r * BROWS;
                cp16(bdst + (uint32_t)(row * BPITCH + b_ch) * 2,
                     Bg0 + (size_t)(k0 + row) * ldb + b_ch);
            }
        }
    };

    float c[2][2 * NJ][4];
#pragma unroll
    for (int mi = 0; mi < 2; mi++)
#pragma unroll
        for (int j = 0; j < 2 * NJ; j++)
#pragma unroll
            for (int q = 0; q < 4; q++) c[mi][j][q] = 0.0f;

#pragma unroll
    for (int s = 0; s < NST - 1; s++) {
        if (s < nk) issue(s, s);
        CP_COMMIT();
    }

    const uint32_t a_lane_off = (uint32_t)((lane & 15) * APITCH + ((lane >> 4) << 3)) * 2;
    const uint32_t b_lane_off = (uint32_t)((lane & 15) * BPITCH + ((lane >> 4) << 3)) * 2;

    for (int kt = 0; kt < nk; kt++) {
        const int kf = kt + NST - 1;
        if (kf < nk) issue(kf % NST, kf);
        CP_COMMIT();
        asm volatile("cp.async.wait_group %0;" :: "n"(NST - 1) : "memory");
        __syncthreads();

        const int stage = kt % NST;
        const uint32_t ab = sb + stage * STG_BYTES;
        const uint32_t bb = ab + AT * A_STG;

#pragma unroll
        for (int ks = 0; ks < KS; ks++) {
            uint32_t afr[AT][2][4];
            uint32_t bfr[NJ][4];
#pragma unroll
            for (int h = 0; h < AT; h++)
#pragma unroll
                for (int mi = 0; mi < 2; mi++)
                    ldsm4(afr[h][mi],
                          ab + h * A_STG + a_lane_off +
                          (uint32_t)((wm * 32 + mi * 16) * APITCH + ks * 16) * 2);
#pragma unroll
            for (int nj = 0; nj < NJ; nj++)
                ldsm4t(bfr[nj],
                       bb + b_lane_off +
                       (uint32_t)(ks * 16 * BPITCH + wn * WN + nj * 16) * 2);
#pragma unroll
            for (int mi = 0; mi < 2; mi++)
#pragma unroll
                for (int j = 0; j < 2 * NJ; j++) {
                    const int nj = j >> 1, hf = (j & 1) << 1;
                    mma16816(c[mi][j], afr[0][mi], bfr[nj][hf], bfr[nj][hf + 1]);
                    if (AT == 2)
                        mma16816(c[mi][j], afr[1][mi], bfr[nj][hf], bfr[nj][hf + 1]);
                }
        }
        __syncthreads();
    }

    // ---- epilogue ----
    const int colbase = n0 + wn * WN + (lane & 3) * 2;
    if (KHo != nullptr) {
        // K1a routing
#pragma unroll
        for (int mi = 0; mi < 2; mi++)
#pragma unroll
            for (int rr = 0; rr < 2; rr++) {
                const int row = m0 + wm * 32 + mi * 16 + (lane >> 2) + rr * 8;
                if (row >= M2TOT) continue;
                const float bv = bias[row];
                if (row < 64) {
                    __half* qb = QTo + (size_t)b * HW * 64 + row;
#pragma unroll
                    for (int j = 0; j < 2 * NJ; j++) {
                        const int col = colbase + j * 8;
                        qb[(size_t)col * 64]       =
                            __float2half_rn(c[mi][j][rr * 2] + bv);
                        qb[(size_t)(col + 1) * 64] =
                            __float2half_rn(c[mi][j][rr * 2 + 1] + bv);
                    }
                } else if (row < 128) {
                    __half* ph = KHo + ((size_t)b * 64 + (row - 64)) * HW + colbase;
#pragma unroll
                    for (int j = 0; j < 2 * NJ; j++)
                        *reinterpret_cast<__half2*>(ph + j * 8) = __halves2half2(
                            __float2half_rn(c[mi][j][rr * 2] + bv),
                            __float2half_rn(c[mi][j][rr * 2 + 1] + bv));
                } else {
                    float* p = C + (size_t)b * sC + (size_t)(row - 128) * ldc + colbase;
#pragma unroll
                    for (int j = 0; j < 2 * NJ; j++)
                        *reinterpret_cast<float2*>(p + j * 8) =
                            make_float2(c[mi][j][rr * 2] + bv, c[mi][j][rr * 2 + 1] + bv);
                }
            }
    } else if (VHo != nullptr) {
        // K1b: all rows -> VH fp16 (+bias)
#pragma unroll
        for (int mi = 0; mi < 2; mi++)
#pragma unroll
            for (int rr = 0; rr < 2; rr++) {
                const int row = m0 + wm * 32 + mi * 16 + (lane >> 2) + rr * 8;
                const float bv = bias[row];
                __half* ph = VHo + ((size_t)b * 512 + row) * HW + colbase;
#pragma unroll
                for (int j = 0; j < 2 * NJ; j++)
                    *reinterpret_cast<__half2*>(ph + j * 8) = __halves2half2(
                        __float2half_rn(c[mi][j][rr * 2] + bv),
                        __float2half_rn(c[mi][j][rr * 2 + 1] + bv));
            }
    } else if (PEo != nullptr) {
#pragma unroll
        for (int mi = 0; mi < 2; mi++)
#pragma unroll
            for (int rr = 0; rr < 2; rr++) {
                const int rloc = wm * 32 + mi * 16 + (lane >> 2) + rr * 8;
                __half* pp = PEo + ((size_t)b * HW + m0 + rloc) * HW + colbase;
                float rsum = 0.0f;
#pragma unroll
                for (int j = 0; j < 2 * NJ; j++) {
                    float e0 = __expf(c[mi][j][rr * 2]     - 8.0f);
                    float e1 = __expf(c[mi][j][rr * 2 + 1] - 8.0f);
                    __half h0 = __float2half_rn(e0), h1 = __float2half_rn(e1);
                    *reinterpret_cast<__half2*>(pp + j * 8) = __halves2half2(h0, h1);
                    rsum += __half2float(h0) + __half2float(h1);
                }
                rsum += __shfl_xor_sync(0xffffffffu, rsum, 1);
                rsum += __shfl_xor_sync(0xffffffffu, rsum, 2);
                if ((lane & 3) == 0) sred[wn][rloc] = rsum;
            }
        __syncthreads();
        if (tid < 128) {
            float z = sred[0][tid] + sred[1][tid];
            Part[((size_t)b * gridDim.y + blockIdx.y) * HW + m0 + tid] = z;
        }
    } else {
#pragma unroll
        for (int mi = 0; mi < 2; mi++) {
            const int r0 = m0 + wm * 32 + mi * 16 + (lane >> 2);
            const float bv0 = has_bias ? bias[r0]     : 0.0f;
            const float bv1 = has_bias ? bias[r0 + 8] : 0.0f;
            float* p0 = C + (size_t)b * sC + (size_t)r0 * ldc + colbase;
            float* p1 = p0 + (size_t)8 * ldc;
#pragma unroll
            for (int j = 0; j < 2 * NJ; j++) {
                *reinterpret_cast<float2*>(p0 + j * 8) =
                    make_float2(c[mi][j][0] + bv0, c[mi][j][1] + bv0);
                *reinterpret_cast<float2*>(p1 + j * 8) =
                    make_float2(c[mi][j][2] + bv1, c[mi][j][3] + bv1);
            }
        }
    }
}

#define SM_AT2   (3 * (2 * 128 * 40 * 2 + 32 * 136 * 2))   // 87552
#define SM_AT1   (3 * (1 * 128 * 40 * 2 + 32 * 136 * 2))   // 56832
#define SM_AT1_4 (4 * (1 * 128 * 40 * 2 + 32 * 136 * 2))   // 75776

// ---------------------------------------------------------------------------
// Z reduction + v column scaling
// ---------------------------------------------------------------------------
__global__ void zinv_k(const float* __restrict__ Part, float* __restrict__ zinv)
{
    int i = blockIdx.x * 256 + threadIdx.x;
    int b = i >> 12, r = i & 4095;
    float s = 0.0f;
#pragma unroll
    for (int jt = 0; jt < 32; jt++) s += Part[((size_t)b * 32 + jt) * HW + r];
    zinv[i] = 1.0f / s;
}

__global__ void vscale_k(__half* __restrict__ VH, const float* __restrict__ zinv)
{
    const int b = blockIdx.y;
    int idx = blockIdx.x * 256 + threadIdx.x;
    int c  = idx >> 11;
    int i2 = idx & 2047;
    __half2* p = reinterpret_cast<__half2*>(VH + ((size_t)b * 512 + c) * HW) + i2;
    float2 f = __half22float2(*p);
    float z0 = zinv[(size_t)b * HW + 2 * i2];
    float z1 = zinv[(size_t)b * HW + 2 * i2 + 1];
    *p = __floats2half2_rn(f.x * z0, f.y * z1);
}

// ---------------------------------------------------------------------------
// fp16 conversions / packing (direct from inputs)
// ---------------------------------------------------------------------------
__global__ void tohalf4(const float* __restrict__ in, __half* __restrict__ hi,
                        int count4, size_t in_bs, size_t out_bs)
{
    size_t b = blockIdx.y;
    int i = blockIdx.x * 256 + threadIdx.x;
    if (i >= count4) return;
    float4 v = reinterpret_cast<const float4*>(in + b * in_bs)[i];
    __half2* ph = reinterpret_cast<__half2*>(hi + b * out_bs);
    ph[2 * i]     = __floats2half2_rn(v.x, v.y);
    ph[2 * i + 1] = __floats2half2_rn(v.z, v.w);
}

// one-kernel packing: weights split (5 mats), v weights fp16, biases.
// blocks [0,768): splitW5 work; [768,1792): v weights; [1792,1796): biases
__global__ void pack_all(
    const float* __restrict__ pq, const float* __restrict__ pk,
    const float* __restrict__ cq, const float* __restrict__ ck,
    const float* __restrict__ cv, const float* __restrict__ pv,
    const float* __restrict__ pqb, const float* __restrict__ pkb,
    const float* __restrict__ cqb, const float* __restrict__ ckb,
    const float* __restrict__ cvb, const float* __restrict__ pvb,
    __half* __restrict__ W2H, __half* __restrict__ W2L,
    __half* __restrict__ WVH, float* __restrict__ BI2, float* __restrict__ BIV)
{
    const int blk = blockIdx.x;
    const int tid = threadIdx.x;
    if (blk < 768) {
        int i = blk * 256 + tid;                // 0 .. M2PAD*CH-1
        int row = i >> 9, col = i & 511;
        float v = 0.0f;
        if (row < 64)        v = pq[(size_t)row * 512 + col];
        else if (row < 128)  v = pk[(size_t)(row - 64) * 512 + col];
        else if (row < 192)  v = cq[(size_t)(row - 128) * 512 + col];
        else if (row < 256)  v = ck[(size_t)(row - 192) * 512 + col];
        else if (row < 320)  v = cv[(size_t)(row - 256) * 512 + col];
        __half h = __float2half_rn(v);
        W2H[i] = h;
        W2L[i] = __float2half_rn(v - __half2float(h));
    } else if (blk < 1792) {
        int i = (blk - 768) * 256 + tid;        // 0 .. CH*CH-1
        WVH[i] = __float2half_rn(pv[i]);
    } else {
        int i = (blk - 1792) * 256 + tid;       // 0 .. 895
        if (i < 384) {
            float v = 0.0f;
            if (i < 64)        v = pqb[i];
            else if (i < 128)  v = pkb[i - 64];
            else if (i < 192)  v = cqb[i - 128];
            else if (i < 256)  v = ckb[i - 192];
            else if (i < 320)  v = cvb[i - 256];
            BI2[i] = v;
        } else if (i < 896) {
            BIV[i - 384] = pvb[i - 384];
        }
    }
}

// ---------------------------------------------------------------------------
// SIMT f32x2 GEMM (small K8 accumulate)
// ---------------------------------------------------------------------------
__device__ __forceinline__ unsigned long long pk2(float lo, float hi) {
    unsigned long long r;
    asm("mov.b64 %0, {%1, %2};" : "=l"(r) : "f"(lo), "f"(hi));
    return r;
}
__device__ __forceinline__ unsigned long long fma2(unsigned long long a,
                                                   unsigned long long b,
                                                   unsigned long long c) {
    unsigned long long d;
    asm("fma.rn.f32x2 %0, %1, %2, %3;" : "=l"(d) : "l"(a), "l"(b), "l"(c));
    return d;
}
__device__ __forceinline__ float2 u2f(unsigned long long u) {
    float2 f;
    asm("mov.b64 {%0, %1}, %2;" : "=f"(f.x), "=f"(f.y) : "l"(u));
    return f;
}

__global__ __launch_bounds__(256, 2)
void gemm_acc(const float* __restrict__ A, const float* __restrict__ Bm,
              const float* __restrict__ bias, float* __restrict__ Cm,
              int M, int N, int K, int lda, int ldb, int ldc,
              size_t sA, size_t sB, size_t sC)
{
    __shared__ float As[16][128 + 4];
    __shared__ float Bs[16][128];

    const int b  = blockIdx.z;
    const float* Ab = A + (size_t)b * sA;
    const float* Bb = Bm + (size_t)b * sB;
    float*       Cb = Cm + (size_t)b * sC;

    const int m0 = blockIdx.y * 128;
    const int n0 = blockIdx.x * 128;
    const int t  = threadIdx.x;
    const int tm0 = (t >> 4) << 3;
    const int tn0 = (t & 15) << 3;

    unsigned long long acc[8][4];
#pragma unroll
    for (int i = 0; i < 8; i++)
#pragma unroll
        for (int j = 0; j < 4; j++) acc[i][j] = 0ull;

    for (int k0 = 0; k0 < K; k0 += 16) {
#pragma unroll
        for (int r = 0; r < 2; r++) {
            int idx = t + r * 256;
            int row = idx >> 2;
            int c4  = (idx & 3) << 2;
            float4 v = make_float4(0.f, 0.f, 0.f, 0.f);
            if (m0 + row < M)
                v = *reinterpret_cast<const float4*>(Ab + (size_t)(m0 + row) * lda + k0 + c4);
            As[c4 + 0][row] = v.x; As[c4 + 1][row] = v.y;
            As[c4 + 2][row] = v.z; As[c4 + 3][row] = v.w;
        }
#pragma unroll
        for (int r = 0; r < 2; r++) {
            int idx = t + r * 256;
            int kr  = idx >> 5;
            int n4  = (idx & 31) << 2;
            float4 v = *reinterpret_cast<const float4*>(Bb + (size_t)(k0 + kr) * ldb + n0 + n4);
            *reinterpret_cast<float4*>(&Bs[kr][n4]) = v;
        }
        __syncthreads();
#pragma unroll
        for (int kk = 0; kk < 16; kk++) {
            float4 a0 = *reinterpret_cast<const float4*>(&As[kk][tm0]);
            float4 a1 = *reinterpret_cast<const float4*>(&As[kk][tm0 + 4]);
            ulonglong2 bl0 = *reinterpret_cast<const ulonglong2*>(&Bs[kk][tn0]);
            ulonglong2 bl1 = *reinterpret_cast<const ulonglong2*>(&Bs[kk][tn0 + 4]);
            unsigned long long bv[4] = {bl0.x, bl0.y, bl1.x, bl1.y};
            float av[8] = {a0.x, a0.y, a0.z, a0.w, a1.x, a1.y, a1.z, a1.w};
#pragma unroll
            for (int i = 0; i < 8; i++) {
                unsigned long long a2 = pk2(av[i], av[i]);
#pragma unroll
                for (int j = 0; j < 4; j++) acc[i][j] = fma2(a2, bv[j], acc[i][j]);
            }
        }
        __syncthreads();
    }
#pragma unroll
    for (int i = 0; i < 8; i++) {
        int m = m0 + tm0 + i;
        if (m >= M) continue;
        float bsv = bias[m];
        float* crow = Cb + (size_t)m * ldc + n0 + tn0;
#pragma unroll
        for (int j = 0; j < 4; j++) {
            float2 f = u2f(acc[i][j]);
            float2 o = *reinterpret_cast<const float2*>(crow + j * 2);
            f.x += bsv + o.x; f.y += bsv + o.y;
            *reinterpret_cast<float2*>(crow + j * 2) = f;
        }
    }
}

// ---------------------------------------------------------------------------
// Channel attention kernels (fp32, small; Y rows/batch: cq 0, ck 64, cv 128)
// ---------------------------------------------------------------------------
__global__ void chan_energy(const float* __restrict__ cq, const float* __restrict__ ck,
                            float* __restrict__ part)
{
    __shared__ float sq[64][65];
    __shared__ float sk[64][65];
    const int b = blockIdx.y;
    const int split = blockIdx.x;
    const float* cqb = cq + (size_t)b * YROWS * HW;
    const float* ckb = ck + (size_t)b * YROWS * HW;
    const int t = threadIdx.x;
    const int p0 = (t >> 4) * 4;
    const int q0 = (t & 15) * 4;

    float acc[4][4];
#pragma unroll
    for (int i = 0; i < 4; i++)
#pragma unroll
        for (int j = 0; j < 4; j++) acc[i][j] = 0.f;

    for (int c = 0; c < 4; c++) {
        const int nb = (split * 4 + c) * 64;
        __syncthreads();
#pragma unroll
        for (int i = 0; i < 16; i++) {
            int idx = t + i * 256;
            int row = idx >> 6, col = idx & 63;
            sq[row][col] = cqb[(size_t)row * HW + nb + col];
            sk[row][col] = ckb[(size_t)row * HW + nb + col];
        }
        __syncthreads();
        for (int nn = 0; nn < 64; nn++) {
            float aq[4], bk[4];
#pragma unroll
            for (int i = 0; i < 4; i++) aq[i] = sq[p0 + i][nn];
#pragma unroll
            for (int j = 0; j < 4; j++) bk[j] = sk[q0 + j][nn];
#pragma unroll
            for (int i = 0; i < 4; i++)
#pragma unroll
                for (int j = 0; j < 4; j++) acc[i][j] += aq[i] * bk[j];
        }
    }
    float* out = part + (size_t)split * (BATCH * 4096) + (size_t)b * 4096;
#pragma unroll
    for (int i = 0; i < 4; i++)
#pragma unroll
        for (int j = 0; j < 4; j++)
            out[(p0 + i) * 64 + (q0 + j)] = acc[i][j];
}

__global__ void reduce_ce(const float* __restrict__ part, float* __restrict__ cE)
{
    int i = blockIdx.x * 256 + threadIdx.x;
    float s = 0.f;
#pragma unroll
    for (int k = 0; k < 16; k++) s += part[(size_t)k * (BATCH * 4096) + i];
    cE[i] = s;
}

__global__ void chan_softmax(float* __restrict__ cE)
{
    __shared__ float red[64];
    const int row = blockIdx.x;
    float* rp = cE + (size_t)row * 64;
    const int t = threadIdx.x;
    float v = rp[t];
    red[t] = v; __syncthreads();
    for (int s = 32; s > 0; s >>= 1) {
        if (t < s) red[t] = fmaxf(red[t], red[t + s]);
        __syncthreads();
    }
    float m = red[0]; __syncthreads();
    float e = __expf(v - m);
    red[t] = e; __syncthreads();
    for (int s = 32; s > 0; s >>= 1) {
        if (t < s) red[t] += red[t + s];
        __syncthreads();
    }
    rp[t] = e / red[0];
}

__global__ void chan_out(const float* __restrict__ cattn, const float* __restrict__ cv,
                         float* __restrict__ cout)
{
    __shared__ float sa[4096];
    const int b = blockIdx.y;
    const int n = blockIdx.x * 256 + threadIdx.x;
    const float* at = cattn + (size_t)b * 4096;
    for (int i = threadIdx.x; i < 4096; i += 256) sa[i] = at[i];
    __syncthreads();

    const float* cvb = cv + (size_t)b * YROWS * HW;
    float acc[64];
#pragma unroll
    for (int p = 0; p < 64; p++) acc[p] = 0.f;
    for (int q = 0; q < 64; q++) {
        float vv = cvb[(size_t)q * HW + n];
#pragma unroll
        for (int p = 0; p < 64; p++) acc[p] += sa[p * 64 + q] * vv;
    }
    float* ob = cout + (size_t)b * CQD * HW;
#pragma unroll
    for (int p = 0; p < 64; p++) ob[(size_t)p * HW + n] = acc[p];
}

// ---------------------------------------------------------------------------
// Launch: two-stream; s2 carries K1b (v projection) + channel path
// ---------------------------------------------------------------------------
extern "C" void kernel_launch(void* const* d_in, const int* in_sizes, int n_in,
                              void* d_out, int out_size)
{
    (void)in_sizes; (void)n_in; (void)out_size;

    static cudaStream_t s2 = nullptr;
    static cudaEvent_t evFork = nullptr, evV = nullptr, evJoin = nullptr;
    if (s2 == nullptr) {
        cudaStreamCreateWithFlags(&s2, cudaStreamNonBlocking);
        cudaEventCreateWithFlags(&evFork, cudaEventDisableTiming);
        cudaEventCreateWithFlags(&evV, cudaEventDisableTiming);
        cudaEventCreateWithFlags(&evJoin, cudaEventDisableTiming);
    }

    const float* x = (const float*)d_in[0];

    float* S = nullptr;
    cudaGetSymbolAddress((void**)&S, g_scratch);

    float* BI2  = S + OFF_BI;
    float* BIV  = S + OFF_BI + 384;
    float* Y    = S + OFF_Y;
    float* PART = S + OFF_PART;
    float* ZINV = S + OFF_ZINV;
    float* CE   = S + OFF_CE;
    float* CEP  = S + OFF_CEP;
    float* CO   = S + OFF_CO;
    float* out  = (float*)d_out;

    __half* W2H = (__half*)(S + OFF_W2H);
    __half* W2L = (__half*)(S + OFF_W2L);
    __half* WVH = (__half*)(S + OFF_WVH);
    __half* XH  = (__half*)(S + OFF_XH);
    __half* QTH = (__half*)(S + OFF_QTH);
    __half* KH  = (__half*)(S + OFF_KH);
    __half* VH  = (__half*)(S + OFF_VH);
    __half* PH  = (__half*)(S + OFF_PH);

    cudaFuncSetAttribute((const void*)gemm_mma<2, 32, 3, 128, 2>,
                         cudaFuncAttributeMaxDynamicSharedMemorySize, SM_AT2);
    cudaFuncSetAttribute((const void*)gemm_mma<1, 32, 3, 128, 2>,
                         cudaFuncAttributeMaxDynamicSharedMemorySize, SM_AT1);
    cudaFuncSetAttribute((const void*)gemm_mma<1, 32, 4, 128, 2>,
                         cudaFuncAttributeMaxDynamicSharedMemorySize, SM_AT1_4);

    // packing / conversions (single pack kernel + x conversion)
    pack_all<<<1796, 256>>>(
        (const float*)d_in[1], (const float*)d_in[3], (const float*)d_in[7],
        (const float*)d_in[9], (const float*)d_in[11], (const float*)d_in[5],
        (const float*)d_in[2], (const float*)d_in[4], (const float*)d_in[8],
        (const float*)d_in[10], (const float*)d_in[12], (const float*)d_in[6],
        W2H, W2L, WVH, BI2, BIV);
    tohalf4<<<dim3(2048, BATCH), 256>>>(x, XH, 524288, (size_t)CH * HW, (size_t)CH * HW);

    // K1a: q,k,channel projections (2-term), routed epilogue
    gemm_mma<2, 32, 3, 128, 2><<<dim3(3, 32, BATCH), 256, SM_AT2>>>(
        W2H, W2L, XH, BI2, Y, 512, 512, HW, HW,
        (size_t)0, (size_t)CH * HW, (size_t)YROWS * HW, 1, QTH, KH, nullptr,
        nullptr, nullptr);

    // ---- fork: K1b (v projection) + channel path on s2 ----
    cudaEventRecord(evFork, 0);
    cudaStreamWaitEvent(s2, evFork, 0);

    // K1b: v = fp16(Wv @ x + bias)  (1-term)
    gemm_mma<1, 32, 3, 128, 2><<<dim3(4, 32, BATCH), 256, SM_AT1, s2>>>(
        WVH, nullptr, XH, BIV, nullptr, 512, 512, HW, 0,
        (size_t)0, (size_t)CH * HW, (size_t)0, 1, nullptr, nullptr, VH,
        nullptr, nullptr);
    cudaEventRecord(evV, s2);

    chan_energy<<<dim3(16, BATCH), 256, 0, s2>>>(Y, Y + (size_t)64 * HW, CEP);
    reduce_ce<<<128, 256, 0, s2>>>(CEP, CE);
    chan_softmax<<<BATCH * 64, 64, 0, s2>>>(CE);
    chan_out<<<dim3(16, BATCH), 256, 0, s2>>>(CE, Y + (size_t)128 * HW, CO);
    cudaEventRecord(evJoin, s2);

    // ---- main stream: position path ----
    gemm_mma<1, 32, 3, 128, 2><<<dim3(32, 32, BATCH), 256, SM_AT1>>>(
        QTH, nullptr, KH, nullptr, nullptr, 64, 64, HW, 0,
        (size_t)HW * 64, (size_t)64 * HW, (size_t)0, 0,
        nullptr, nullptr, nullptr, PH, PART);

    zinv_k<<<BATCH * HW / 256, 256>>>(PART, ZINV);

    // vscale needs VH from K1b
    cudaStreamWaitEvent(0, evV, 0);
    vscale_k<<<dim3(4096, BATCH), 256>>>(VH, ZINV);

    // K4: pos_out = vscaled @ PE  (deeper 4-stage pipeline)
    gemm_mma<1, 32, 4, 128, 2><<<dim3(4, 32, BATCH), 256, SM_AT1_4>>>(
        VH, nullptr, PH, nullptr, out, HW, HW, HW, HW,
        (size_t)CH * HW, (size_t)HW * HW, (size_t)CH * HW, 0,
        nullptr, nullptr, nullptr, nullptr, nullptr);

    // ---- join ----
    cudaStreamWaitEvent(0, evJoin, 0);

    // K8: d_out += co_w @ c_out + co_b (SIMT)
    gemm_acc<<<dim3(32, 4, BATCH), 256>>>(
        (const float*)d_in[13], CO, (const float*)d_in[14], out,
        CH, HW, CQD, CQD, HW, HW,
        (size_t)0, (size_t)CQD * HW, (size_t)CH * HW);
}